// round 15
// baseline (speedup 1.0000x reference)
#include <cuda_runtime.h>
#include <cuda_bf16.h>
#include <cstdint>

// HashEmbedding gather: out[row,:] = embedding[hashed_ids[row],:]
// rows = 32768, D = 1024 fp32 = 256 float4 per row.
//
// R15: champion warp-per-row config (tied best bench 29.184us) with
// 512-thread blocks: 16 warps = 16 rows per block, grid 2048. Halves
// CTA count for better wave-tail balance; all data-path parameters
// unchanged (warp-uniform id load, 8x float4 gathers MLP=8, 8x
// contiguous evict-first 128-bit stores).
//
// Session conclusion baked into this config: the kernel is bound by
// the 134MB DRAM write stream at ~4.8 TB/s effective write bandwidth.
// Proven by convergence of 7 structural families (MLP 2-8, SW pipeline,
// TMA bulk DMA, bucket dedup with 35% less LTS traffic, width x hint
// matrix, thread-geometry variants) at 27.2-28.5us kernel; dedup with
// LESS traffic ran slower; issue <=5%, occ ~80% throughout.

static constexpr int D_F4 = 256;          // float4 per row
static constexpr int THREADS = 512;       // 16 warps
static constexpr int ROWS_PER_BLK = 16;   // 1 row per warp

__global__ void __launch_bounds__(THREADS)
hash_embedding_gather(const int* __restrict__ hashed_ids,
                      const float4* __restrict__ emb,
                      float4* __restrict__ out,
                      int nrows)
{
    const int warp = threadIdx.x >> 5;
    const int lane = threadIdx.x & 31;

    const int row = blockIdx.x * ROWS_PER_BLK + warp;
    if (row >= nrows) return;

    // Warp-uniform id load: one address across the warp (UR path).
    const int id = __ldg(hashed_ids + row);

    const float4* __restrict__ src = emb + (size_t)id  * D_F4;
    float4*       __restrict__ dst = out + (size_t)row * D_F4;

    // 8 independent coalesced gathers, front-batched (MLP=8 per lane).
    float4 v0 = __ldg(src + lane);
    float4 v1 = __ldg(src + lane + 32);
    float4 v2 = __ldg(src + lane + 64);
    float4 v3 = __ldg(src + lane + 96);
    float4 v4 = __ldg(src + lane + 128);
    float4 v5 = __ldg(src + lane + 160);
    float4 v6 = __ldg(src + lane + 192);
    float4 v7 = __ldg(src + lane + 224);

    // Evict-first 128-bit stores, 512B contiguous per instruction.
    __stcs(dst + lane,       v0);
    __stcs(dst + lane + 32,  v1);
    __stcs(dst + lane + 64,  v2);
    __stcs(dst + lane + 96,  v3);
    __stcs(dst + lane + 128, v4);
    __stcs(dst + lane + 160, v5);
    __stcs(dst + lane + 192, v6);
    __stcs(dst + lane + 224, v7);
}

extern "C" void kernel_launch(void* const* d_in, const int* in_sizes, int n_in,
                              void* d_out, int out_size)
{
    // metadata order: input_ids (unused), hashed_ids (int32), embedding (fp32)
    const int*    hashed_ids = (const int*)d_in[1];
    const float4* emb        = (const float4*)d_in[2];
    float4*       out        = (float4*)d_out;

    int nrows = in_sizes[1];   // 32768
    int blocks = (nrows + ROWS_PER_BLK - 1) / ROWS_PER_BLK;

    hash_embedding_gather<<<blocks, THREADS>>>(hashed_ids, emb, out, nrows);
}

// round 16
// speedup vs baseline: 1.0074x; 1.0074x over previous
#include <cuda_runtime.h>
#include <cuda_bf16.h>
#include <cstdint>

// HashEmbedding gather: out[row,:] = embedding[hashed_ids[row],:]
// rows = 32768, D = 1024 fp32 = 256 float4 per row.
//
// FINAL (R14 config, tied-best bench 29.184us; kernel 27.2-27.5us).
// One warp per 4KB row, 8 warps per 256-thread block, grid 4096:
//  - warp-uniform id load (one request + broadcast)
//  - 8 independent coalesced float4 gathers per lane (MLP=8)
//  - 8 contiguous evict-first (.cs) 128-bit stores (512B/instruction;
//    keeps the 40MB table L2-resident; worth ~1us vs plain/wt/v8)
//
// Measured conclusion after 15 rounds / 7 structural families (MLP 2-8,
// persistent SW pipeline, TMA bulk DMA, bucket dedup, width x cache-hint
// matrix, thread geometries 128-512): bound by the 134MB DRAM write
// stream at ~4.8 TB/s effective write bandwidth. Dedup with 35% less
// LTS traffic ran SLOWER (falsifies crossbar-bound); issue <=5% and
// occ 72-80% throughout (falsifies SM-bound). ~27us kernel is the
// hardware floor for this problem on GB300.

static constexpr int D_F4 = 256;          // float4 per row
static constexpr int THREADS = 256;       // 8 warps
static constexpr int ROWS_PER_BLK = 8;    // 1 row per warp

__global__ void __launch_bounds__(THREADS)
hash_embedding_gather(const int* __restrict__ hashed_ids,
                      const float4* __restrict__ emb,
                      float4* __restrict__ out,
                      int nrows)
{
    const int warp = threadIdx.x >> 5;
    const int lane = threadIdx.x & 31;

    const int row = blockIdx.x * ROWS_PER_BLK + warp;
    if (row >= nrows) return;

    // Warp-uniform id load: one address across the warp.
    const int id = __ldg(hashed_ids + row);

    const float4* __restrict__ src = emb + (size_t)id  * D_F4;
    float4*       __restrict__ dst = out + (size_t)row * D_F4;

    // 8 independent coalesced gathers, front-batched (MLP=8 per lane).
    float4 v0 = __ldg(src + lane);
    float4 v1 = __ldg(src + lane + 32);
    float4 v2 = __ldg(src + lane + 64);
    float4 v3 = __ldg(src + lane + 96);
    float4 v4 = __ldg(src + lane + 128);
    float4 v5 = __ldg(src + lane + 160);
    float4 v6 = __ldg(src + lane + 192);
    float4 v7 = __ldg(src + lane + 224);

    // Evict-first 128-bit stores, 512B contiguous per instruction.
    __stcs(dst + lane,       v0);
    __stcs(dst + lane + 32,  v1);
    __stcs(dst + lane + 64,  v2);
    __stcs(dst + lane + 96,  v3);
    __stcs(dst + lane + 128, v4);
    __stcs(dst + lane + 160, v5);
    __stcs(dst + lane + 192, v6);
    __stcs(dst + lane + 224, v7);
}

extern "C" void kernel_launch(void* const* d_in, const int* in_sizes, int n_in,
                              void* d_out, int out_size)
{
    // metadata order: input_ids (unused), hashed_ids (int32), embedding (fp32)
    const int*    hashed_ids = (const int*)d_in[1];
    const float4* emb        = (const float4*)d_in[2];
    float4*       out        = (float4*)d_out;

    int nrows = in_sizes[1];   // 32768
    int blocks = (nrows + ROWS_PER_BLK - 1) / ROWS_PER_BLK;

    hash_embedding_gather<<<blocks, THREADS>>>(hashed_ids, emb, out, nrows);
}

// round 17
// speedup vs baseline: 1.0439x; 1.0362x over previous
#include <cuda_runtime.h>
#include <cuda_bf16.h>
#include <cstdint>

// HashEmbedding gather: out[row,:] = embedding[hashed_ids[row],:]
// rows = 32768, D = 1024 fp32 = 256 float4 per row.
//
// FINAL — champion configuration (best measured bench: 29.184us, twice;
// kernel 27.2-27.7us across runs, run-to-run noise +-0.7us).
//
// One warp per 4KB row, 8 warps per 256-thread block, grid 4096:
//  - warp-uniform id load (one request + broadcast)
//  - 8 independent coalesced float4 gathers per lane (MLP=8)
//  - 8 contiguous evict-first (.cs) 128-bit stores (512B/instruction;
//    keeps the 40MB table L2-resident; ~1us better than plain/wt/v8)
//
// Established over 16 rounds / 7 structural families (MLP 2-16,
// persistent SW pipeline, TMA bulk DMA both directions, bucket dedup,
// store-width x cache-hint matrix, thread geometries 128-512):
// the kernel is bound by the mandatory 134MB DRAM write stream at
// ~4.8 TB/s effective write bandwidth. Dedup cutting LTS traffic 35%
// ran SLOWER (not crossbar-bound); issue <=5%, occ 72-83% (not
// SM-bound); all well-coalesced variants converge at 27.2-28.5us.
// ~27us kernel is the hardware floor for this problem on GB300.

static constexpr int D_F4 = 256;          // float4 per row
static constexpr int THREADS = 256;       // 8 warps
static constexpr int ROWS_PER_BLK = 8;    // 1 row per warp

__global__ void __launch_bounds__(THREADS)
hash_embedding_gather(const int* __restrict__ hashed_ids,
                      const float4* __restrict__ emb,
                      float4* __restrict__ out,
                      int nrows)
{
    const int warp = threadIdx.x >> 5;
    const int lane = threadIdx.x & 31;

    const int row = blockIdx.x * ROWS_PER_BLK + warp;
    if (row >= nrows) return;

    // Warp-uniform id load: one address across the warp.
    const int id = __ldg(hashed_ids + row);

    const float4* __restrict__ src = emb + (size_t)id  * D_F4;
    float4*       __restrict__ dst = out + (size_t)row * D_F4;

    // 8 independent coalesced gathers, front-batched (MLP=8 per lane).
    float4 v0 = __ldg(src + lane);
    float4 v1 = __ldg(src + lane + 32);
    float4 v2 = __ldg(src + lane + 64);
    float4 v3 = __ldg(src + lane + 96);
    float4 v4 = __ldg(src + lane + 128);
    float4 v5 = __ldg(src + lane + 160);
    float4 v6 = __ldg(src + lane + 192);
    float4 v7 = __ldg(src + lane + 224);

    // Evict-first 128-bit stores, 512B contiguous per instruction.
    __stcs(dst + lane,       v0);
    __stcs(dst + lane + 32,  v1);
    __stcs(dst + lane + 64,  v2);
    __stcs(dst + lane + 96,  v3);
    __stcs(dst + lane + 128, v4);
    __stcs(dst + lane + 160, v5);
    __stcs(dst + lane + 192, v6);
    __stcs(dst + lane + 224, v7);
}

extern "C" void kernel_launch(void* const* d_in, const int* in_sizes, int n_in,
                              void* d_out, int out_size)
{
    // metadata order: input_ids (unused), hashed_ids (int32), embedding (fp32)
    const int*    hashed_ids = (const int*)d_in[1];
    const float4* emb        = (const float4*)d_in[2];
    float4*       out        = (float4*)d_out;

    int nrows = in_sizes[1];   // 32768
    int blocks = (nrows + ROWS_PER_BLK - 1) / ROWS_PER_BLK;

    hash_embedding_gather<<<blocks, THREADS>>>(hashed_ids, emb, out, nrows);
}